// round 7
// baseline (speedup 1.0000x reference)
#include <cuda_runtime.h>
#include <cuda_bf16.h>
#include <stdint.h>

#define BATCH 16384
#define KS 20
#define DIM 256
#define NH 4
#define EPSF 1e-8f

typedef __nv_bfloat16 bf16;

// ---------------- scratch (device globals; allocations are forbidden) ------
__device__ bf16 g_xh [(long)BATCH * 256], g_xl [(long)BATCH * 256];
__device__ bf16 g_mh [(long)BATCH * 256], g_ml [(long)BATCH * 256];  // hmean
__device__ bf16 g_qh [(long)BATCH * 256], g_ql [(long)BATCH * 256];
__device__ bf16 g_sh [(long)BATCH * 1024], g_sl [(long)BATCH * 1024];
__device__ bf16 g_ch [(long)BATCH * 256], g_cl [(long)BATCH * 256];
#define W_TOTAL 425984
__device__ bf16 g_wh[W_TOTAL], g_wl[W_TOTAL];
__device__ float g_had [(long)BATCH * 128];
__device__ float g_himp[(long)BATCH * 256];
__device__ float g_qk  [(long)BATCH * 1024];
__device__ float g_N   [(long)BATCH * 1024];   // partial numerator (j>=1)
__device__ float g_Z   [(long)BATCH * NH];     // partial denominator (j>=1)
__device__ float g_dot0[(long)BATCH * NH];     // (qk_h . x)/8
__device__ float g_stat[BATCH];

__device__ __forceinline__ float warp_sum(float v) {
    #pragma unroll
    for (int o = 16; o; o >>= 1) v += __shfl_down_sync(0xffffffffu, v, o);
    return v;
}
__device__ __forceinline__ void store_split(bf16* ph, bf16* pl, float v) {
    bf16 h = __float2bfloat16(v);
    *ph = h;
    *pl = __float2bfloat16(v - __bfloat162float(h));
}

// ---------------- conv_w: one-shot weight conversion (+ Wk transpose) ------
// layout in g_wh/g_wl:
//   [0,32768)        ad_w1   [128][256]
//   [32768,163840)   imp_w1  [256][512]
//   [163840,229376)  wq      [256][256]
//   [229376,294912)  wkT     [4][256 n][64 i]   (transposed)
//   [294912,360448)  wv      [256][256]
//   [360448,425984)  w_out   [256][256]
__global__ __launch_bounds__(256) void conv_w(
    const float* __restrict__ ad_w1, const float* __restrict__ imp_w1,
    const float* __restrict__ w_in,  const float* __restrict__ w_out)
{
    int i = blockIdx.x * 256 + threadIdx.x;
    if (i >= W_TOTAL) return;
    float v;
    if (i < 32768)       v = ad_w1[i];
    else if (i < 163840) v = imp_w1[i - 32768];
    else if (i < 229376) v = w_in[i - 163840];
    else if (i < 294912) {
        int j = i - 229376;
        int z = j >> 14, r = (j >> 6) & 255, c = j & 63;
        v = w_in[65536 + (z * 64 + c) * 256 + r];
    }
    else if (i < 360448) v = w_in[131072 + (i - 294912)];
    else                 v = w_out[i - 360448];
    bf16 h = __float2bfloat16(v);
    g_wh[i] = h;
    g_wl[i] = __float2bfloat16(v - __bfloat162float(h));
}

// ---------------- conv_x: x -> bf16 hi/lo ----------------------------------
__global__ __launch_bounds__(256) void conv_x(const float* __restrict__ x)
{
    long i = (long)blockIdx.x * 256 + threadIdx.x;
    store_split(g_xh + i, g_xl + i, x[i]);
}

// ---------------- K1: stats + st rows 1..19 + attention partials -----------
__global__ __launch_bounds__(256) void k1_stats(
    const float* __restrict__ storage, const float* __restrict__ xmsg,
    float* __restrict__ out_st)
{
    __shared__ float sm[KS][DIM];
    __shared__ float qks[NH * DIM];
    __shared__ float xs[DIM];
    __shared__ float smask[KS];
    __shared__ float sred[8];
    __shared__ float sc[NH][KS];   // e_j values, col jj used for j=jj+1

    int b = blockIdx.x, tid = threadIdx.x;
    const float* row = storage + (long)b * KS * DIM;
    #pragma unroll
    for (int j = 0; j < KS; j++) sm[j][tid] = row[j * DIM + tid];
    xs[tid] = xmsg[(long)b * DIM + tid];
    #pragma unroll
    for (int h = 0; h < NH; h++)
        qks[h * DIM + tid] = g_qk[(long)b * 1024 + h * DIM + tid];
    __syncthreads();

    int w = tid >> 5, lane = tid & 31;
    for (int j = w; j < KS; j += 8) {
        float s = 0.f;
        #pragma unroll
        for (int i = lane; i < DIM; i += 32) s += fabsf(sm[j][i]);
        s = warp_sum(s);
        if (lane == 0) smask[j] = (s > 0.f) ? 1.f : 0.f;
    }
    __syncthreads();

    float denom = EPSF;
    #pragma unroll
    for (int j = 0; j < KS; j++) denom += smask[j];

    int d = tid;
    float m = 0.f;
    #pragma unroll
    for (int j = 0; j < KS; j++) m += sm[j][d] * smask[j];
    float hmean = m / denom;
    float v = 0.f;
    #pragma unroll
    for (int j = 0; j < KS; j++) {
        float df = sm[j][d] - hmean;
        v += df * df * smask[j];
    }
    float hstd = sqrtf(v / denom);

    float xd = xs[d];
    float z = fabsf((xd - hmean) / (hstd + EPSF));
    float c = (z > 2.0f) ? 1.f : 0.f;
    c = warp_sum(c);
    if (lane == 0) sred[w] = c;
    __syncthreads();
    if (tid == 0) {
        float t = 0.f;
        #pragma unroll
        for (int i = 0; i < 8; i++) t += sred[i];
        g_stat[b] = t / (float)DIM;
    }

    store_split(g_mh + (long)b * 256 + d, g_ml + (long)b * 256 + d, hmean);

    // decay-in-place: sm[jj] <- storage[jj]*0.95^jj = st[jj+1]; write rows 1..19
    float dec = 1.f;
    float* orow = out_st + (long)b * KS * DIM;
    #pragma unroll
    for (int jj = 0; jj < KS - 1; jj++) {
        float sv = sm[jj][d] * dec;
        sm[jj][d] = sv;
        orow[(jj + 1) * DIM + d] = sv;
        dec *= 0.95f;
    }
    __syncthreads();

    // scores: 76 tasks (h, jj) for st rows 1..19 + 4 tasks for qk.x
    for (int id = w; id < 80; id += 8) {
        float s = 0.f;
        if (id < 76) {
            int h = id / 19, jj = id % 19;
            const float* qh = qks + h * DIM;
            #pragma unroll
            for (int i = lane; i < DIM; i += 32) s += qh[i] * sm[jj][i];
            s = warp_sum(s);
            if (lane == 0) sc[h][jj] = expf(s * 0.125f);
        } else {
            int h = id - 76;
            const float* qh = qks + h * DIM;
            #pragma unroll
            for (int i = lane; i < DIM; i += 32) s += qh[i] * xs[i];
            s = warp_sum(s);
            if (lane == 0) g_dot0[(long)b * NH + h] = s * 0.125f;
        }
    }
    __syncthreads();

    if (tid < NH) {
        float zz = 0.f;
        #pragma unroll
        for (int jj = 0; jj < KS - 1; jj++) zz += sc[tid][jj];
        g_Z[(long)b * NH + tid] = zz;
    }

    float acc[NH] = {0.f, 0.f, 0.f, 0.f};
    #pragma unroll
    for (int jj = 0; jj < KS - 1; jj++) {
        float sv = sm[jj][d];
        #pragma unroll
        for (int h = 0; h < NH; h++) acc[h] += sc[h][jj] * sv;
    }
    #pragma unroll
    for (int h = 0; h < NH; h++)
        g_N[(long)b * 1024 + h * DIM + d] = acc[h];
}

// ---------------- kf: anomaly + importance + st row0 + final attention -----
__global__ __launch_bounds__(256) void kf(
    const float* __restrict__ ad_w2, const float* __restrict__ ad_b2,
    const float* __restrict__ imp_w2, const float* __restrict__ imp_b2,
    const float* __restrict__ xmsg, float* __restrict__ out_st)
{
    __shared__ float sred1[8], sred2[8], se0[NH], sfac[NH];
    __shared__ float simp;
    int b = blockIdx.x, tid = threadIdx.x;
    int w = tid >> 5, lane = tid & 31;

    float p1 = (tid < 128) ? g_had[(long)b * 128 + tid] * ad_w2[tid] : 0.f;
    float p2 = g_himp[(long)b * 256 + tid] * imp_w2[tid];
    p1 = warp_sum(p1);
    p2 = warp_sum(p2);
    if (lane == 0) { sred1[w] = p1; sred2[w] = p2; }
    __syncthreads();
    if (tid == 0) {
        float d1 = ad_b2[0], d2 = imp_b2[0];
        #pragma unroll
        for (int i = 0; i < 8; i++) { d1 += sred1[i]; d2 += sred2[i]; }
        float learned = 1.f / (1.f + expf(-d1));
        float anom = 0.5f * g_stat[b] + 0.5f * learned;
        float sp = fmaxf(d2, 0.f) + log1pf(expf(-fabsf(d2)));
        simp = sp * (1.f + anom);
    }
    __syncthreads();
    float imp = simp;
    if (tid < NH) {
        float e0 = expf(imp * g_dot0[(long)b * NH + tid]);
        se0[tid] = e0;
        sfac[tid] = 1.f / (g_Z[(long)b * NH + tid] + e0);
    }
    float x = xmsg[(long)b * 256 + tid];
    float st0 = x * imp;
    out_st[(long)b * KS * DIM + tid] = st0;
    __syncthreads();

    #pragma unroll
    for (int h = 0; h < NH; h++) {
        float s = (g_N[(long)b * 1024 + h * 256 + tid] + se0[h] * st0) * sfac[h];
        long o = (long)b * 1024 + h * 256 + tid;
        store_split(g_sh + o, g_sl + o, s);
    }
}

// ---------------- bf16x3 TC GEMM, 128x64 tile, preconverted operands -------
// C(m, cZ*z + n0+n) = act( sum_k A[m*lda + aZ*z + k] * W[(n0+n)*ldb + bZ*z + k] + bias )
#define PADA 136
#define PADB 72

__device__ __forceinline__ void mma16816(float* c, const uint32_t* a,
                                         const uint32_t* b) {
    asm volatile(
        "mma.sync.aligned.m16n8k16.row.col.f32.bf16.bf16.f32 "
        "{%0,%1,%2,%3},{%4,%5,%6,%7},{%8,%9},{%0,%1,%2,%3};"
        : "+f"(c[0]), "+f"(c[1]), "+f"(c[2]), "+f"(c[3])
        : "r"(a[0]), "r"(a[1]), "r"(a[2]), "r"(a[3]), "r"(b[0]), "r"(b[1]));
}

__global__ __launch_bounds__(256) void gemm_tc(
    int aSel, int lda, int aZ, int splitK,
    int wOff, int ldb, int bZ,
    const float* __restrict__ bias, int biasZ,
    float* __restrict__ Cext, int cSel, int cBfSel,
    int ldc, int cZ, int Ktot, int act)
{
    __shared__ uint32_t Ahs[16][PADA], Als[16][PADA];
    __shared__ uint32_t Bhs[16][PADB], Bls[16][PADB];

    const bf16 *Ah, *Al;
    switch (aSel) {
        case 1: case 2: Ah = g_xh; Al = g_xl; break;
        case 3:  Ah = g_qh;  Al = g_ql;  break;
        case 4:  Ah = g_sh;  Al = g_sl;  break;
        default: Ah = g_ch;  Al = g_cl;  break;
    }
    float* Cf = Cext;
    if (cSel == 2) Cf = g_had;
    else if (cSel == 3) Cf = g_himp;
    else if (cSel == 5) Cf = g_qk;

    int z  = blockIdx.z;
    int m0 = blockIdx.x * 128;
    int n0 = blockIdx.y * 64;
    long aOff = (long)aZ * z;
    long bOff = (long)wOff + (long)bZ * z;

    int tid = threadIdx.x;
    int warp = tid >> 5, lane = tid & 31;
    int wm = (warp >> 1) * 32, wn = (warp & 1) * 32;
    int lr = lane >> 2, lc = lane & 3;

    float acc[2][4][4];
    #pragma unroll
    for (int i = 0; i < 2; i++)
        #pragma unroll
        for (int j = 0; j < 4; j++)
            #pragma unroll
            for (int q = 0; q < 4; q++) acc[i][j][q] = 0.f;

    for (int c0 = 0; c0 < Ktot; c0 += 32) {
        // ---- A tile 128x32 bf16 pairs (direct copy) ----
        {
            int arow = tid >> 1, seg = (tid & 1) * 16;
            int kg = c0 + seg;
            const bf16* bh_ = Ah;
            const bf16* bl_ = Al;
            int kk = kg;
            if (kg >= splitK) {           // dual-A (imp): second half = hmean
                bh_ = g_mh; bl_ = g_ml; kk = kg - splitK;
            }
            long gp = (long)(m0 + arow) * lda + aOff + kk;
            uint4 vh0 = *(const uint4*)(bh_ + gp);
            uint4 vh1 = *(const uint4*)(bh_ + gp + 8);
            uint4 vl0 = *(const uint4*)(bl_ + gp);
            uint4 vl1 = *(const uint4*)(bl_ + gp + 8);
            int kp0 = seg >> 1;
            Ahs[kp0 + 0][arow] = vh0.x; Ahs[kp0 + 1][arow] = vh0.y;
            Ahs[kp0 + 2][arow] = vh0.z; Ahs[kp0 + 3][arow] = vh0.w;
            Ahs[kp0 + 4][arow] = vh1.x; Ahs[kp0 + 5][arow] = vh1.y;
            Ahs[kp0 + 6][arow] = vh1.z; Ahs[kp0 + 7][arow] = vh1.w;
            Als[kp0 + 0][arow] = vl0.x; Als[kp0 + 1][arow] = vl0.y;
            Als[kp0 + 2][arow] = vl0.z; Als[kp0 + 3][arow] = vl0.w;
            Als[kp0 + 4][arow] = vl1.x; Als[kp0 + 5][arow] = vl1.y;
            Als[kp0 + 6][arow] = vl1.z; Als[kp0 + 7][arow] = vl1.w;
        }
        // ---- B tile 64x32 bf16 pairs ----
        {
            int n = tid >> 2, kq = (tid & 3) * 8;
            long gp = bOff + (long)(n0 + n) * ldb + c0 + kq;
            uint4 vh = *(const uint4*)(g_wh + gp);
            uint4 vl = *(const uint4*)(g_wl + gp);
            int kp0 = kq >> 1;
            Bhs[kp0 + 0][n] = vh.x; Bhs[kp0 + 1][n] = vh.y;
            Bhs[kp0 + 2][n] = vh.z; Bhs[kp0 + 3][n] = vh.w;
            Bls[kp0 + 0][n] = vl.x; Bls[kp0 + 1][n] = vl.y;
            Bls[kp0 + 2][n] = vl.z; Bls[kp0 + 3][n] = vl.w;
        }
        __syncthreads();

        #pragma unroll
        for (int ks = 0; ks < 2; ks++) {
            int kpb = ks * 8;
            uint32_t ah[2][4], al[2][4], bh[4][2], bl[4][2];
            #pragma unroll
            for (int am = 0; am < 2; am++) {
                int r = wm + am * 16 + lr;
                ah[am][0] = Ahs[kpb + lc][r];
                ah[am][1] = Ahs[kpb + lc][r + 8];
                ah[am][2] = Ahs[kpb + 4 + lc][r];
                ah[am][3] = Ahs[kpb + 4 + lc][r + 8];
                al[am][0] = Als[kpb + lc][r];
                al[am][1] = Als[kpb + lc][r + 8];
                al[am][2] = Als[kpb + 4 + lc][r];
                al[am][3] = Als[kpb + 4 + lc][r + 8];
            }
            #pragma unroll
            for (int an = 0; an < 4; an++) {
                int n = wn + an * 8 + lr;
                bh[an][0] = Bhs[kpb + lc][n];
                bh[an][1] = Bhs[kpb + 4 + lc][n];
                bl[an][0] = Bls[kpb + lc][n];
                bl[an][1] = Bls[kpb + 4 + lc][n];
            }
            // interleaved (R3-proven): per-accumulator hh/hl/lh triplets
            #pragma unroll
            for (int am = 0; am < 2; am++)
                #pragma unroll
                for (int an = 0; an < 4; an++) {
                    mma16816(acc[am][an], ah[am], bh[an]);
                    mma16816(acc[am][an], ah[am], bl[an]);
                    mma16816(acc[am][an], al[am], bh[an]);
                }
        }
        __syncthreads();
    }

    // ---- epilogue ----
    #pragma unroll
    for (int am = 0; am < 2; am++) {
        #pragma unroll
        for (int an = 0; an < 4; an++) {
            int row0 = m0 + wm + am * 16 + lr;
            int col  = n0 + wn + an * 8 + lc * 2;
            float b0 = 0.f, b1 = 0.f;
            if (bias) {
                b0 = bias[biasZ * z + col];
                b1 = bias[biasZ * z + col + 1];
            }
            float v0 = acc[am][an][0] + b0, v1 = acc[am][an][1] + b1;
            float v2 = acc[am][an][2] + b0, v3 = acc[am][an][3] + b1;
            if (act == 1) {
                v0 = fmaxf(v0, 0.f); v1 = fmaxf(v1, 0.f);
                v2 = fmaxf(v2, 0.f); v3 = fmaxf(v3, 0.f);
            }
            long off = (long)cZ * z + col;
            if (cBfSel) {
                bf16* Ch = (cBfSel == 1) ? g_qh : g_ch;
                bf16* Cl = (cBfSel == 1) ? g_ql : g_cl;
                long p0 = (long)row0 * ldc + off;
                long p1 = (long)(row0 + 8) * ldc + off;
                store_split(Ch + p0, Cl + p0, v0);
                store_split(Ch + p0 + 1, Cl + p0 + 1, v1);
                store_split(Ch + p1, Cl + p1, v2);
                store_split(Ch + p1 + 1, Cl + p1 + 1, v3);
            } else {
                *(float2*)(Cf + (long)row0 * ldc + off) = make_float2(v0, v1);
                *(float2*)(Cf + (long)(row0 + 8) * ldc + off) = make_float2(v2, v3);
            }
        }
    }
}

#define NOSPLIT (1 << 30)

// ---------------------------------------------------------------------------
extern "C" void kernel_launch(void* const* d_in, const int* in_sizes, int n_in,
                              void* d_out, int out_size) {
    const float* storage = (const float*)d_in[0];
    const float* x       = (const float*)d_in[1];
    const float* ad_w1   = (const float*)d_in[2];
    const float* ad_b1   = (const float*)d_in[3];
    const float* ad_w2   = (const float*)d_in[4];
    const float* ad_b2   = (const float*)d_in[5];
    const float* imp_w1  = (const float*)d_in[6];
    const float* imp_b1  = (const float*)d_in[7];
    const float* imp_w2  = (const float*)d_in[8];
    const float* imp_b2  = (const float*)d_in[9];
    const float* w_in    = (const float*)d_in[10];
    const float* b_in    = (const float*)d_in[11];
    const float* w_out   = (const float*)d_in[12];
    const float* b_out   = (const float*)d_in[13];

    float* st  = (float*)d_out;                       // [B,K,D]
    float* agg = st + (long)BATCH * KS * DIM;         // [B,D]

    conv_w<<<(W_TOTAL + 255) / 256, 256>>>(ad_w1, imp_w1, w_in, w_out);
    conv_x<<<BATCH, 256>>>(x);
    // q = x @ wq^T + bq -> g_qh/g_ql [B,256]
    gemm_tc<<<dim3(128, 4, 1), 256>>>(1, 256, 0, NOSPLIT, 163840, 256, 0,
                                      b_in, 0, nullptr, 0, 1, 256, 0, 256, 0);
    // qk[b, z*256+n] = wkT[z][n][:] . q[b, z*64:] -> g_qk fp32
    gemm_tc<<<dim3(128, 4, 4), 256>>>(3, 256, 64, NOSPLIT, 229376, 64, 16384,
                                      nullptr, 0, nullptr, 5, 0, 1024, 256, 64, 0);
    // stats + st rows 1..19 + attention partials (N1, Z1, dot0)
    k1_stats<<<BATCH, 256>>>(storage, x, st);
    // ad-MLP hidden: relu(x @ ad_w1^T + ad_b1) -> g_had [B,128]
    gemm_tc<<<dim3(128, 2, 1), 256>>>(1, 256, 0, NOSPLIT, 0, 256, 0,
                                      ad_b1, 0, nullptr, 2, 0, 128, 0, 256, 1);
    // imp-MLP hidden: relu([x|hmean] @ imp_w1^T + imp_b1) -> g_himp [B,256]
    gemm_tc<<<dim3(128, 4, 1), 256>>>(2, 256, 0, 256, 32768, 512, 0,
                                      imp_b1, 0, nullptr, 3, 0, 256, 0, 512, 1);
    // anomaly + importance + st row0 + final weighted sums -> g_sh/g_sl
    kf<<<BATCH, 256>>>(ad_w2, ad_b2, imp_w2, imp_b2, x, st);
    // ctx[b, z*64+n] = wv_z[n,:] . s[b,z,:] + bv -> g_ch/g_cl [B,256]
    gemm_tc<<<dim3(128, 1, 4), 256>>>(4, 1024, 256, NOSPLIT, 294912, 256, 16384,
                                      b_in + 512, 64, nullptr, 0, 2, 256, 64, 256, 0);
    // agg = ctx @ attn_out_w^T + attn_out_b -> d_out tail (fp32)
    gemm_tc<<<dim3(128, 4, 1), 256>>>(5, 256, 0, NOSPLIT, 360448, 256, 0,
                                      b_out, 0, agg, 0, 0, 256, 0, 256, 0);
    (void)in_sizes; (void)n_in; (void)out_size;
}

// round 8
// speedup vs baseline: 1.1621x; 1.1621x over previous
#include <cuda_runtime.h>
#include <cuda_bf16.h>
#include <stdint.h>

#define BATCH 16384
#define KS 20
#define DIM 256
#define NH 4
#define EPSF 1e-8f

typedef __nv_bfloat16 bf16;

// ---------------- scratch (device globals; allocations are forbidden) ------
__device__ bf16 g_xh [(long)BATCH * 256], g_xl [(long)BATCH * 256];
__device__ bf16 g_mh [(long)BATCH * 256], g_ml [(long)BATCH * 256];  // hmean
__device__ bf16 g_qh [(long)BATCH * 256], g_ql [(long)BATCH * 256];
__device__ bf16 g_sh [(long)BATCH * 1024], g_sl [(long)BATCH * 1024];
__device__ bf16 g_ch [(long)BATCH * 256], g_cl [(long)BATCH * 256];
#define W_TOTAL 425984
__device__ bf16 g_wh[W_TOTAL], g_wl[W_TOTAL];
__device__ float g_had [(long)BATCH * 128];
__device__ float g_himp[(long)BATCH * 256];
__device__ float g_qk  [(long)BATCH * 1024];
__device__ float g_N   [(long)BATCH * 1024];
__device__ float g_Z   [(long)BATCH * NH];
__device__ float g_dot0[(long)BATCH * NH];
__device__ float g_stat[BATCH];

__device__ __forceinline__ float warp_sum(float v) {
    #pragma unroll
    for (int o = 16; o; o >>= 1) v += __shfl_down_sync(0xffffffffu, v, o);
    return v;
}
__device__ __forceinline__ void store_split(bf16* ph, bf16* pl, float v) {
    bf16 h = __float2bfloat16(v);
    *ph = h;
    *pl = __float2bfloat16(v - __bfloat162float(h));
}

// ---------------- conv_w: one-shot weight conversion (+ Wk transpose) ------
__global__ __launch_bounds__(256) void conv_w(
    const float* __restrict__ ad_w1, const float* __restrict__ imp_w1,
    const float* __restrict__ w_in,  const float* __restrict__ w_out)
{
    int i = blockIdx.x * 256 + threadIdx.x;
    if (i >= W_TOTAL) return;
    float v;
    if (i < 32768)       v = ad_w1[i];
    else if (i < 163840) v = imp_w1[i - 32768];
    else if (i < 229376) v = w_in[i - 163840];
    else if (i < 294912) {
        int j = i - 229376;
        int z = j >> 14, r = (j >> 6) & 255, c = j & 63;
        v = w_in[65536 + (z * 64 + c) * 256 + r];
    }
    else if (i < 360448) v = w_in[131072 + (i - 294912)];
    else                 v = w_out[i - 360448];
    bf16 h = __float2bfloat16(v);
    g_wh[i] = h;
    g_wl[i] = __float2bfloat16(v - __bfloat162float(h));
}

__global__ __launch_bounds__(256) void conv_x(const float* __restrict__ x)
{
    long i = (long)blockIdx.x * 256 + threadIdx.x;
    store_split(g_xh + i, g_xl + i, x[i]);
}

// ---------------- K1: stats + st rows 1..19 + attention partials -----------
__global__ __launch_bounds__(256) void k1_stats(
    const float* __restrict__ storage, const float* __restrict__ xmsg,
    float* __restrict__ out_st)
{
    __shared__ float sm[KS][DIM];
    __shared__ float qks[NH * DIM];
    __shared__ float xs[DIM];
    __shared__ float smask[KS];
    __shared__ float sred[8];
    __shared__ float sc[NH][KS];

    int b = blockIdx.x, tid = threadIdx.x;
    const float* row = storage + (long)b * KS * DIM;
    #pragma unroll
    for (int j = 0; j < KS; j++) sm[j][tid] = row[j * DIM + tid];
    xs[tid] = xmsg[(long)b * DIM + tid];
    #pragma unroll
    for (int h = 0; h < NH; h++)
        qks[h * DIM + tid] = g_qk[(long)b * 1024 + h * DIM + tid];
    __syncthreads();

    int w = tid >> 5, lane = tid & 31;
    for (int j = w; j < KS; j += 8) {
        float s = 0.f;
        #pragma unroll
        for (int i = lane; i < DIM; i += 32) s += fabsf(sm[j][i]);
        s = warp_sum(s);
        if (lane == 0) smask[j] = (s > 0.f) ? 1.f : 0.f;
    }
    __syncthreads();

    float denom = EPSF;
    #pragma unroll
    for (int j = 0; j < KS; j++) denom += smask[j];

    int d = tid;
    float m = 0.f;
    #pragma unroll
    for (int j = 0; j < KS; j++) m += sm[j][d] * smask[j];
    float hmean = m / denom;
    float v = 0.f;
    #pragma unroll
    for (int j = 0; j < KS; j++) {
        float df = sm[j][d] - hmean;
        v += df * df * smask[j];
    }
    float hstd = sqrtf(v / denom);

    float xd = xs[d];
    float z = fabsf((xd - hmean) / (hstd + EPSF));
    float c = (z > 2.0f) ? 1.f : 0.f;
    c = warp_sum(c);
    if (lane == 0) sred[w] = c;
    __syncthreads();
    if (tid == 0) {
        float t = 0.f;
        #pragma unroll
        for (int i = 0; i < 8; i++) t += sred[i];
        g_stat[b] = t / (float)DIM;
    }

    store_split(g_mh + (long)b * 256 + d, g_ml + (long)b * 256 + d, hmean);

    float dec = 1.f;
    float* orow = out_st + (long)b * KS * DIM;
    #pragma unroll
    for (int jj = 0; jj < KS - 1; jj++) {
        float sv = sm[jj][d] * dec;
        sm[jj][d] = sv;
        orow[(jj + 1) * DIM + d] = sv;
        dec *= 0.95f;
    }
    __syncthreads();

    for (int id = w; id < 80; id += 8) {
        float s = 0.f;
        if (id < 76) {
            int h = id / 19, jj = id % 19;
            const float* qh = qks + h * DIM;
            #pragma unroll
            for (int i = lane; i < DIM; i += 32) s += qh[i] * sm[jj][i];
            s = warp_sum(s);
            if (lane == 0) sc[h][jj] = expf(s * 0.125f);
        } else {
            int h = id - 76;
            const float* qh = qks + h * DIM;
            #pragma unroll
            for (int i = lane; i < DIM; i += 32) s += qh[i] * xs[i];
            s = warp_sum(s);
            if (lane == 0) g_dot0[(long)b * NH + h] = s * 0.125f;
        }
    }
    __syncthreads();

    if (tid < NH) {
        float zz = 0.f;
        #pragma unroll
        for (int jj = 0; jj < KS - 1; jj++) zz += sc[tid][jj];
        g_Z[(long)b * NH + tid] = zz;
    }

    float acc[NH] = {0.f, 0.f, 0.f, 0.f};
    #pragma unroll
    for (int jj = 0; jj < KS - 1; jj++) {
        float sv = sm[jj][d];
        #pragma unroll
        for (int h = 0; h < NH; h++) acc[h] += sc[h][jj] * sv;
    }
    #pragma unroll
    for (int h = 0; h < NH; h++)
        g_N[(long)b * 1024 + h * DIM + d] = acc[h];
}

// ---------------- kf: anomaly + importance + st row0 + final attention -----
__global__ __launch_bounds__(256) void kf(
    const float* __restrict__ ad_w2, const float* __restrict__ ad_b2,
    const float* __restrict__ imp_w2, const float* __restrict__ imp_b2,
    const float* __restrict__ xmsg, float* __restrict__ out_st)
{
    __shared__ float sred1[8], sred2[8], se0[NH], sfac[NH];
    __shared__ float simp;
    int b = blockIdx.x, tid = threadIdx.x;
    int w = tid >> 5, lane = tid & 31;

    float p1 = (tid < 128) ? g_had[(long)b * 128 + tid] * ad_w2[tid] : 0.f;
    float p2 = g_himp[(long)b * 256 + tid] * imp_w2[tid];
    p1 = warp_sum(p1);
    p2 = warp_sum(p2);
    if (lane == 0) { sred1[w] = p1; sred2[w] = p2; }
    __syncthreads();
    if (tid == 0) {
        float d1 = ad_b2[0], d2 = imp_b2[0];
        #pragma unroll
        for (int i = 0; i < 8; i++) { d1 += sred1[i]; d2 += sred2[i]; }
        float learned = 1.f / (1.f + expf(-d1));
        float anom = 0.5f * g_stat[b] + 0.5f * learned;
        float sp = fmaxf(d2, 0.f) + log1pf(expf(-fabsf(d2)));
        simp = sp * (1.f + anom);
    }
    __syncthreads();
    float imp = simp;
    if (tid < NH) {
        float e0 = expf(imp * g_dot0[(long)b * NH + tid]);
        se0[tid] = e0;
        sfac[tid] = 1.f / (g_Z[(long)b * NH + tid] + e0);
    }
    float x = xmsg[(long)b * 256 + tid];
    float st0 = x * imp;
    out_st[(long)b * KS * DIM + tid] = st0;
    __syncthreads();

    #pragma unroll
    for (int h = 0; h < NH; h++) {
        float s = (g_N[(long)b * 1024 + h * 256 + tid] + se0[h] * st0) * sfac[h];
        long o = (long)b * 1024 + h * 256 + tid;
        store_split(g_sh + o, g_sl + o, s);
    }
}

// ---------------- pipelined bf16x3 TC GEMM, 128x64 tile --------------------
// cp.async 2-stage double buffer; row-major smem (80B pitch); ldmatrix frags.
#define PITCH 80
#define SZ_A 10240              // 128 rows * 80 B
#define SZ_B 5120               // 64 rows * 80 B
#define OFF_AL (SZ_A)
#define OFF_BH (2 * SZ_A)
#define OFF_BL (2 * SZ_A + SZ_B)
#define STAGE  (2 * SZ_A + 2 * SZ_B)   // 30720
#define SMEM_DYN (2 * STAGE)           // 61440

#define CP16(dst, src) asm volatile( \
    "cp.async.cg.shared.global [%0], [%1], 16;" :: "r"(dst), "l"(src))
#define CP_COMMIT() asm volatile("cp.async.commit_group;" ::: "memory")
#define CP_WAIT1()  asm volatile("cp.async.wait_group 1;" ::: "memory")
#define CP_WAIT0()  asm volatile("cp.async.wait_group 0;" ::: "memory")

__device__ __forceinline__ void ldmx4(uint32_t* r, uint32_t addr) {
    asm volatile("ldmatrix.sync.aligned.m8n8.x4.shared.b16 {%0,%1,%2,%3},[%4];"
                 : "=r"(r[0]), "=r"(r[1]), "=r"(r[2]), "=r"(r[3]) : "r"(addr));
}
__device__ __forceinline__ void mma16816(float* c, const uint32_t* a,
                                         const uint32_t* b) {
    asm volatile(
        "mma.sync.aligned.m16n8k16.row.col.f32.bf16.bf16.f32 "
        "{%0,%1,%2,%3},{%4,%5,%6,%7},{%8,%9},{%0,%1,%2,%3};"
        : "+f"(c[0]), "+f"(c[1]), "+f"(c[2]), "+f"(c[3])
        : "r"(a[0]), "r"(a[1]), "r"(a[2]), "r"(a[3]), "r"(b[0]), "r"(b[1]));
}
__device__ __forceinline__ uint32_t smem_u32(const void* p) {
    return (uint32_t)__cvta_generic_to_shared(p);
}

template<int ASEL, int KTOT, int SPLITK, int CBF, int ACT>
__global__ __launch_bounds__(256, 2) void gemm_pl(
    int lda, int aZ, int wOff, int ldb, int bZ,
    const float* __restrict__ bias, int biasZ,
    float* __restrict__ Cext, int cSel, int ldc, int cZ)
{
    extern __shared__ __align__(128) char dsm[];
    uint32_t sm0 = smem_u32(dsm);

    const bf16 *Ah, *Al;
    if (ASEL == 1 || ASEL == 2) { Ah = g_xh; Al = g_xl; }
    else if (ASEL == 3) { Ah = g_qh; Al = g_ql; }
    else if (ASEL == 4) { Ah = g_sh; Al = g_sl; }
    else                { Ah = g_ch; Al = g_cl; }
    float* Cf = Cext;
    if (cSel == 2) Cf = g_had;
    else if (cSel == 3) Cf = g_himp;
    else if (cSel == 5) Cf = g_qk;

    int z  = blockIdx.z;
    int m0 = blockIdx.x * 128;
    int n0 = blockIdx.y * 64;
    long aOff = (long)aZ * z;
    long bOff = (long)wOff + (long)bZ * z;

    int tid = threadIdx.x;
    int warp = tid >> 5, lane = tid & 31;
    int wm = (warp >> 1) * 32, wn = (warp & 1) * 32;
    int lr = lane >> 2, lc = lane & 3;

    // loader thread mapping
    int arow = tid >> 1, acs = (tid & 1) * 2;   // 2x16B chunks of a 64B row
    int brow = tid >> 2, bcs = tid & 3;         // 1x16B chunk
    uint32_t aDst = arow * PITCH + acs * 16;
    uint32_t bDst = brow * PITCH + bcs * 16;
    long aRowOff = (long)(m0 + arow) * lda + aOff + acs * 8;
    long bSrc = bOff + (long)(n0 + brow) * ldb + bcs * 8;

    // fragment lane offsets
    uint32_t aFrag = (uint32_t)((wm + (lane & 15)) * PITCH + (lane >> 4) * 16);
    uint32_t bFrag = (uint32_t)((wn + ((lane >> 4) << 3) + (lane & 7)) * PITCH
                                + ((lane >> 3) & 1) * 16);

    const int NCH = KTOT / 32;

    auto issue = [&](int ch, int st) {
        uint32_t sb = sm0 + st * STAGE;
        int c0 = ch * 32;
        const bf16* ah_ = Ah;
        const bf16* al_ = Al;
        int kk = c0;
        if (SPLITK < KTOT && c0 >= SPLITK) { ah_ = g_mh; al_ = g_ml; kk = c0 - SPLITK; }
        long ga = aRowOff + kk;
        CP16(sb + aDst,            ah_ + ga);
        CP16(sb + aDst + 16,       ah_ + ga + 8);
        CP16(sb + OFF_AL + aDst,       al_ + ga);
        CP16(sb + OFF_AL + aDst + 16,  al_ + ga + 8);
        long gb = bSrc + c0;
        CP16(sb + OFF_BH + bDst, g_wh + gb);
        CP16(sb + OFF_BL + bDst, g_wl + gb);
    };

    float acc[2][4][4];
    #pragma unroll
    for (int i = 0; i < 2; i++)
        #pragma unroll
        for (int j = 0; j < 4; j++)
            #pragma unroll
            for (int q = 0; q < 4; q++) acc[i][j][q] = 0.f;

    issue(0, 0);
    CP_COMMIT();

    #pragma unroll
    for (int ch = 0; ch < NCH; ch++) {
        int st = ch & 1;
        if (ch + 1 < NCH) {
            issue(ch + 1, (ch + 1) & 1);
            CP_COMMIT();
            CP_WAIT1();
        } else {
            CP_WAIT0();
        }
        __syncthreads();

        uint32_t sb = sm0 + st * STAGE;
        #pragma unroll
        for (int ks = 0; ks < 2; ks++) {
            uint32_t kb = ks * 32;
            uint32_t ah[2][4], al[2][4], bh[2][4], bl[2][4];
            #pragma unroll
            for (int am = 0; am < 2; am++) {
                ldmx4(ah[am], sb + aFrag + am * (16 * PITCH) + kb);
                ldmx4(al[am], sb + OFF_AL + aFrag + am * (16 * PITCH) + kb);
            }
            #pragma unroll
            for (int anp = 0; anp < 2; anp++) {
                ldmx4(bh[anp], sb + OFF_BH + bFrag + anp * (16 * PITCH) + kb);
                ldmx4(bl[anp], sb + OFF_BL + bFrag + anp * (16 * PITCH) + kb);
            }
            #pragma unroll
            for (int am = 0; am < 2; am++)
                #pragma unroll
                for (int an = 0; an < 4; an++) {
                    const uint32_t* bph = &bh[an >> 1][(an & 1) * 2];
                    const uint32_t* bpl = &bl[an >> 1][(an & 1) * 2];
                    mma16816(acc[am][an], ah[am], bph);
                    mma16816(acc[am][an], ah[am], bpl);
                    mma16816(acc[am][an], al[am], bph);
                }
        }
        __syncthreads();
    }

    // ---- epilogue ----
    #pragma unroll
    for (int am = 0; am < 2; am++) {
        #pragma unroll
        for (int an = 0; an < 4; an++) {
            int row0 = m0 + wm + am * 16 + lr;
            int col  = n0 + wn + an * 8 + lc * 2;
            float b0 = 0.f, b1 = 0.f;
            if (bias) {
                b0 = bias[biasZ * z + col];
                b1 = bias[biasZ * z + col + 1];
            }
            float v0 = acc[am][an][0] + b0, v1 = acc[am][an][1] + b1;
            float v2 = acc[am][an][2] + b0, v3 = acc[am][an][3] + b1;
            if (ACT == 1) {
                v0 = fmaxf(v0, 0.f); v1 = fmaxf(v1, 0.f);
                v2 = fmaxf(v2, 0.f); v3 = fmaxf(v3, 0.f);
            }
            long off = (long)cZ * z + col;
            if (CBF) {
                bf16* Ch = (CBF == 1) ? g_qh : g_ch;
                bf16* Cl = (CBF == 1) ? g_ql : g_cl;
                long p0 = (long)row0 * ldc + off;
                long p1 = (long)(row0 + 8) * ldc + off;
                store_split(Ch + p0, Cl + p0, v0);
                store_split(Ch + p0 + 1, Cl + p0 + 1, v1);
                store_split(Ch + p1, Cl + p1, v2);
                store_split(Ch + p1 + 1, Cl + p1 + 1, v3);
            } else {
                *(float2*)(Cf + (long)row0 * ldc + off) = make_float2(v0, v1);
                *(float2*)(Cf + (long)(row0 + 8) * ldc + off) = make_float2(v2, v3);
            }
        }
    }
}

#define NOSPLIT (1 << 30)

// ---------------------------------------------------------------------------
extern "C" void kernel_launch(void* const* d_in, const int* in_sizes, int n_in,
                              void* d_out, int out_size) {
    const float* storage = (const float*)d_in[0];
    const float* x       = (const float*)d_in[1];
    const float* ad_w1   = (const float*)d_in[2];
    const float* ad_b1   = (const float*)d_in[3];
    const float* ad_w2   = (const float*)d_in[4];
    const float* ad_b2   = (const float*)d_in[5];
    const float* imp_w1  = (const float*)d_in[6];
    const float* imp_b1  = (const float*)d_in[7];
    const float* imp_w2  = (const float*)d_in[8];
    const float* imp_b2  = (const float*)d_in[9];
    const float* w_in    = (const float*)d_in[10];
    const float* b_in    = (const float*)d_in[11];
    const float* w_out   = (const float*)d_in[12];
    const float* b_out   = (const float*)d_in[13];

    float* st  = (float*)d_out;                       // [B,K,D]
    float* agg = st + (long)BATCH * KS * DIM;         // [B,D]

    cudaFuncSetAttribute(gemm_pl<1, 256, NOSPLIT, 1, 0>,
                         cudaFuncAttributeMaxDynamicSharedMemorySize, SMEM_DYN);
    cudaFuncSetAttribute(gemm_pl<3, 64, NOSPLIT, 0, 0>,
                         cudaFuncAttributeMaxDynamicSharedMemorySize, SMEM_DYN);
    cudaFuncSetAttribute(gemm_pl<1, 256, NOSPLIT, 0, 1>,
                         cudaFuncAttributeMaxDynamicSharedMemorySize, SMEM_DYN);
    cudaFuncSetAttribute(gemm_pl<2, 512, 256, 0, 1>,
                         cudaFuncAttributeMaxDynamicSharedMemorySize, SMEM_DYN);
    cudaFuncSetAttribute(gemm_pl<4, 256, NOSPLIT, 2, 0>,
                         cudaFuncAttributeMaxDynamicSharedMemorySize, SMEM_DYN);
    cudaFuncSetAttribute(gemm_pl<5, 256, NOSPLIT, 0, 0>,
                         cudaFuncAttributeMaxDynamicSharedMemorySize, SMEM_DYN);

    conv_w<<<(W_TOTAL + 255) / 256, 256>>>(ad_w1, imp_w1, w_in, w_out);
    conv_x<<<BATCH, 256>>>(x);
    // q = x @ wq^T + bq -> g_qh/g_ql [B,256]
    gemm_pl<1, 256, NOSPLIT, 1, 0><<<dim3(128, 4, 1), 256, SMEM_DYN>>>(
        256, 0, 163840, 256, 0, b_in, 0, nullptr, 0, 256, 0);
    // qk[b, z*256+n] = wkT[z][n][:] . q[b, z*64:] -> g_qk fp32
    gemm_pl<3, 64, NOSPLIT, 0, 0><<<dim3(128, 4, 4), 256, SMEM_DYN>>>(
        256, 64, 229376, 64, 16384, nullptr, 0, nullptr, 5, 1024, 256);
    // stats + st rows 1..19 + attention partials (N1, Z1, dot0)
    k1_stats<<<BATCH, 256>>>(storage, x, st);
    // ad-MLP hidden: relu(x @ ad_w1^T + ad_b1) -> g_had [B,128]
    gemm_pl<1, 256, NOSPLIT, 0, 1><<<dim3(128, 2, 1), 256, SMEM_DYN>>>(
        256, 0, 0, 256, 0, ad_b1, 0, nullptr, 2, 128, 0);
    // imp-MLP hidden: relu([x|hmean] @ imp_w1^T + imp_b1) -> g_himp [B,256]
    gemm_pl<2, 512, 256, 0, 1><<<dim3(128, 4, 1), 256, SMEM_DYN>>>(
        256, 0, 32768, 512, 0, imp_b1, 0, nullptr, 3, 256, 0);
    // anomaly + importance + st row0 + final weighted sums -> g_sh/g_sl
    kf<<<BATCH, 256>>>(ad_w2, ad_b2, imp_w2, imp_b2, x, st);
    // ctx[b, z*64+n] = wv_z[n,:] . s[b,z,:] + bv -> g_ch/g_cl [B,256]
    gemm_pl<4, 256, NOSPLIT, 2, 0><<<dim3(128, 1, 4), 256, SMEM_DYN>>>(
        1024, 256, 294912, 256, 16384, b_in + 512, 64, nullptr, 0, 256, 64);
    // agg = ctx @ attn_out_w^T + attn_out_b -> d_out tail (fp32)
    gemm_pl<5, 256, NOSPLIT, 0, 0><<<dim3(128, 4, 1), 256, SMEM_DYN>>>(
        256, 0, 360448, 256, 0, b_out, 0, agg, 0, 256, 0);
    (void)in_sizes; (void)n_in; (void)out_size;
}

// round 9
// speedup vs baseline: 1.2431x; 1.0697x over previous
#include <cuda_runtime.h>
#include <cuda_bf16.h>
#include <stdint.h>

#define BATCH 16384
#define KS 20
#define DIM 256
#define NH 4
#define EPSF 1e-8f

typedef __nv_bfloat16 bf16;

// ---------------- scratch (device globals; allocations are forbidden) ------
__device__ bf16 g_xh [(long)BATCH * 256], g_xl [(long)BATCH * 256];
__device__ bf16 g_mh [(long)BATCH * 256], g_ml [(long)BATCH * 256];  // hmean
__device__ bf16 g_qh [(long)BATCH * 256], g_ql [(long)BATCH * 256];
__device__ bf16 g_sh [(long)BATCH * 1024], g_sl [(long)BATCH * 1024];
__device__ bf16 g_ch [(long)BATCH * 256], g_cl [(long)BATCH * 256];
#define W_TOTAL 425984
__device__ bf16 g_wh[W_TOTAL], g_wl[W_TOTAL];
__device__ float g_had [(long)BATCH * 128];
__device__ float g_himp[(long)BATCH * 256];
__device__ float g_qk  [(long)BATCH * 1024];
__device__ float g_N   [(long)BATCH * 1024];
__device__ float g_Z   [(long)BATCH * NH];
__device__ float g_dot0[(long)BATCH * NH];
__device__ float g_stat[BATCH];

__device__ __forceinline__ float warp_sum(float v) {
    #pragma unroll
    for (int o = 16; o; o >>= 1) v += __shfl_down_sync(0xffffffffu, v, o);
    return v;
}
__device__ __forceinline__ void store_split(bf16* ph, bf16* pl, float v) {
    bf16 h = __float2bfloat16(v);
    *ph = h;
    *pl = __float2bfloat16(v - __bfloat162float(h));
}

// ---------------- conv_w: one-shot weight conversion (+ Wk transpose) ------
__global__ __launch_bounds__(256) void conv_w(
    const float* __restrict__ ad_w1, const float* __restrict__ imp_w1,
    const float* __restrict__ w_in,  const float* __restrict__ w_out)
{
    int i = blockIdx.x * 256 + threadIdx.x;
    if (i >= W_TOTAL) return;
    float v;
    if (i < 32768)       v = ad_w1[i];
    else if (i < 163840) v = imp_w1[i - 32768];
    else if (i < 229376) v = w_in[i - 163840];
    else if (i < 294912) {
        int j = i - 229376;
        int z = j >> 14, r = (j >> 6) & 255, c = j & 63;
        v = w_in[65536 + (z * 64 + c) * 256 + r];
    }
    else if (i < 360448) v = w_in[131072 + (i - 294912)];
    else                 v = w_out[i - 360448];
    bf16 h = __float2bfloat16(v);
    g_wh[i] = h;
    g_wl[i] = __float2bfloat16(v - __bfloat162float(h));
}

__global__ __launch_bounds__(256) void conv_x(const float* __restrict__ x)
{
    long i = (long)blockIdx.x * 256 + threadIdx.x;
    store_split(g_xh + i, g_xl + i, x[i]);
}

// ---------------- K1: stats + st rows 1..19 + attention partials -----------
__global__ __launch_bounds__(256) void k1_stats(
    const float* __restrict__ storage, const float* __restrict__ xmsg,
    float* __restrict__ out_st)
{
    __shared__ float sm[KS][DIM];
    __shared__ float qks[NH * DIM];
    __shared__ float xs[DIM];
    __shared__ float smask[KS];
    __shared__ float sred[8];
    __shared__ float sc[NH][KS];

    int b = blockIdx.x, tid = threadIdx.x;
    const float* row = storage + (long)b * KS * DIM;
    float vals[KS];
    #pragma unroll
    for (int j = 0; j < KS; j++) {
        vals[j] = row[j * DIM + tid];
        sm[j][tid] = vals[j];
    }
    xs[tid] = xmsg[(long)b * DIM + tid];
    #pragma unroll
    for (int h = 0; h < NH; h++)
        qks[h * DIM + tid] = g_qk[(long)b * 1024 + h * DIM + tid];
    __syncthreads();

    int w = tid >> 5, lane = tid & 31;
    // mask: float4 scans
    for (int j = w; j < KS; j += 8) {
        const float4* sj = (const float4*)sm[j];
        float4 a = sj[lane], c = sj[lane + 32];
        float s = fabsf(a.x) + fabsf(a.y) + fabsf(a.z) + fabsf(a.w)
                + fabsf(c.x) + fabsf(c.y) + fabsf(c.z) + fabsf(c.w);
        s = warp_sum(s);
        if (lane == 0) smask[j] = (s > 0.f) ? 1.f : 0.f;
    }
    __syncthreads();

    float denom = EPSF;
    #pragma unroll
    for (int j = 0; j < KS; j++) denom += smask[j];

    int d = tid;
    float m = 0.f;
    #pragma unroll
    for (int j = 0; j < KS; j++) m += vals[j] * smask[j];
    float hmean = m / denom;
    float v = 0.f;
    #pragma unroll
    for (int j = 0; j < KS; j++) {
        float df = vals[j] - hmean;
        v += df * df * smask[j];
    }
    float hstd = sqrtf(v / denom);

    float xd = xs[d];
    float z = fabsf((xd - hmean) / (hstd + EPSF));
    float c = (z > 2.0f) ? 1.f : 0.f;
    c = warp_sum(c);
    if (lane == 0) sred[w] = c;
    __syncthreads();
    if (tid == 0) {
        float t = 0.f;
        #pragma unroll
        for (int i = 0; i < 8; i++) t += sred[i];
        g_stat[b] = t / (float)DIM;
    }

    store_split(g_mh + (long)b * 256 + d, g_ml + (long)b * 256 + d, hmean);

    // decay: vals[jj] <- storage[jj]*0.95^jj = st[jj+1]; write rows 1..19
    float dec = 1.f;
    float* orow = out_st + (long)b * KS * DIM;
    #pragma unroll
    for (int jj = 0; jj < KS - 1; jj++) {
        float sv = vals[jj] * dec;
        vals[jj] = sv;
        sm[jj][d] = sv;
        orow[(jj + 1) * DIM + d] = sv;
        dec *= 0.95f;
    }
    __syncthreads();

    // scores: 76 tasks (h, jj) + 4 dot0 tasks; 10 per warp, unrolled
    #pragma unroll
    for (int u = 0; u < 10; u++) {
        int id = w + u * 8;
        if (id < 76) {
            int h = id / 19, jj = id % 19;
            const float4* qh = (const float4*)(qks + h * DIM);
            const float4* sj = (const float4*)sm[jj];
            float4 a0 = qh[lane],      b0 = sj[lane];
            float4 a1 = qh[lane + 32], b1 = sj[lane + 32];
            float s = a0.x * b0.x + a0.y * b0.y + a0.z * b0.z + a0.w * b0.w
                    + a1.x * b1.x + a1.y * b1.y + a1.z * b1.z + a1.w * b1.w;
            s = warp_sum(s);
            if (lane == 0) sc[h][jj] = expf(s * 0.125f);
        } else {
            int h = id - 76;
            const float4* qh = (const float4*)(qks + h * DIM);
            const float4* xv = (const float4*)xs;
            float4 a0 = qh[lane],      b0 = xv[lane];
            float4 a1 = qh[lane + 32], b1 = xv[lane + 32];
            float s = a0.x * b0.x + a0.y * b0.y + a0.z * b0.z + a0.w * b0.w
                    + a1.x * b1.x + a1.y * b1.y + a1.z * b1.z + a1.w * b1.w;
            s = warp_sum(s);
            if (lane == 0) g_dot0[(long)b * NH + h] = s * 0.125f;
        }
    }
    __syncthreads();

    if (tid < NH) {
        float zz = 0.f;
        #pragma unroll
        for (int jj = 0; jj < KS - 1; jj++) zz += sc[tid][jj];
        g_Z[(long)b * NH + tid] = zz;
    }

    float acc[NH] = {0.f, 0.f, 0.f, 0.f};
    #pragma unroll
    for (int jj = 0; jj < KS - 1; jj++) {
        float sv = vals[jj];
        #pragma unroll
        for (int h = 0; h < NH; h++) acc[h] += sc[h][jj] * sv;
    }
    #pragma unroll
    for (int h = 0; h < NH; h++)
        g_N[(long)b * 1024 + h * DIM + d] = acc[h];
}

// ---------------- kf: anomaly + importance + st row0 + final attention -----
__global__ __launch_bounds__(256) void kf(
    const float* __restrict__ ad_w2, const float* __restrict__ ad_b2,
    const float* __restrict__ imp_w2, const float* __restrict__ imp_b2,
    const float* __restrict__ xmsg, float* __restrict__ out_st)
{
    __shared__ float sred1[8], sred2[8], se0[NH], sfac[NH];
    __shared__ float simp;
    int b = blockIdx.x, tid = threadIdx.x;
    int w = tid >> 5, lane = tid & 31;

    float p1 = (tid < 128) ? g_had[(long)b * 128 + tid] * ad_w2[tid] : 0.f;
    float p2 = g_himp[(long)b * 256 + tid] * imp_w2[tid];
    p1 = warp_sum(p1);
    p2 = warp_sum(p2);
    if (lane == 0) { sred1[w] = p1; sred2[w] = p2; }
    __syncthreads();
    if (tid == 0) {
        float d1 = ad_b2[0], d2 = imp_b2[0];
        #pragma unroll
        for (int i = 0; i < 8; i++) { d1 += sred1[i]; d2 += sred2[i]; }
        float learned = 1.f / (1.f + expf(-d1));
        float anom = 0.5f * g_stat[b] + 0.5f * learned;
        float sp = fmaxf(d2, 0.f) + log1pf(expf(-fabsf(d2)));
        simp = sp * (1.f + anom);
    }
    __syncthreads();
    float imp = simp;
    if (tid < NH) {
        float e0 = expf(imp * g_dot0[(long)b * NH + tid]);
        se0[tid] = e0;
        sfac[tid] = 1.f / (g_Z[(long)b * NH + tid] + e0);
    }
    float x = xmsg[(long)b * 256 + tid];
    float st0 = x * imp;
    out_st[(long)b * KS * DIM + tid] = st0;
    __syncthreads();

    #pragma unroll
    for (int h = 0; h < NH; h++) {
        float s = (g_N[(long)b * 1024 + h * 256 + tid] + se0[h] * st0) * sfac[h];
        long o = (long)b * 1024 + h * 256 + tid;
        store_split(g_sh + o, g_sl + o, s);
    }
}

// ---------------- pipelined bf16x3 TC GEMM, 128x64 tile, 3 stages ----------
#define PITCH 80
#define SZ_A 10240
#define SZ_B 5120
#define OFF_AL (SZ_A)
#define OFF_BH (2 * SZ_A)
#define OFF_BL (2 * SZ_A + SZ_B)
#define STAGE  (2 * SZ_A + 2 * SZ_B)   // 30720
#define NSTAGE 3
#define SMEM_DYN (NSTAGE * STAGE)      // 92160

#define CP16(dst, src) asm volatile( \
    "cp.async.cg.shared.global [%0], [%1], 16;" :: "r"(dst), "l"(src))
#define CP_COMMIT() asm volatile("cp.async.commit_group;" ::: "memory")
#define CP_WAIT2()  asm volatile("cp.async.wait_group 2;" ::: "memory")
#define CP_WAIT1()  asm volatile("cp.async.wait_group 1;" ::: "memory")
#define CP_WAIT0()  asm volatile("cp.async.wait_group 0;" ::: "memory")

__device__ __forceinline__ void ldmx4(uint32_t* r, uint32_t addr) {
    asm volatile("ldmatrix.sync.aligned.m8n8.x4.shared.b16 {%0,%1,%2,%3},[%4];"
                 : "=r"(r[0]), "=r"(r[1]), "=r"(r[2]), "=r"(r[3]) : "r"(addr));
}
__device__ __forceinline__ void mma16816(float* c, const uint32_t* a,
                                         const uint32_t* b) {
    asm volatile(
        "mma.sync.aligned.m16n8k16.row.col.f32.bf16.bf16.f32 "
        "{%0,%1,%2,%3},{%4,%5,%6,%7},{%8,%9},{%0,%1,%2,%3};"
        : "+f"(c[0]), "+f"(c[1]), "+f"(c[2]), "+f"(c[3])
        : "r"(a[0]), "r"(a[1]), "r"(a[2]), "r"(a[3]), "r"(b[0]), "r"(b[1]));
}
__device__ __forceinline__ uint32_t smem_u32(const void* p) {
    return (uint32_t)__cvta_generic_to_shared(p);
}

template<int ASEL, int KTOT, int SPLITK, int CBF, int ACT>
__global__ __launch_bounds__(256, 2) void gemm_pl(
    int lda, int aZ, int wOff, int ldb, int bZ,
    const float* __restrict__ bias, int biasZ,
    float* __restrict__ Cext, int cSel, int ldc, int cZ)
{
    extern __shared__ __align__(128) char dsm[];
    uint32_t sm0 = smem_u32(dsm);

    const bf16 *Ah, *Al;
    if (ASEL == 1 || ASEL == 2) { Ah = g_xh; Al = g_xl; }
    else if (ASEL == 3) { Ah = g_qh; Al = g_ql; }
    else if (ASEL == 4) { Ah = g_sh; Al = g_sl; }
    else                { Ah = g_ch; Al = g_cl; }
    float* Cf = Cext;
    if (cSel == 2) Cf = g_had;
    else if (cSel == 3) Cf = g_himp;
    else if (cSel == 5) Cf = g_qk;

    int z  = blockIdx.z;
    int m0 = blockIdx.x * 128;
    int n0 = blockIdx.y * 64;
    long aOff = (long)aZ * z;
    long bOff = (long)wOff + (long)bZ * z;

    int tid = threadIdx.x;
    int warp = tid >> 5, lane = tid & 31;
    int wm = (warp >> 1) * 32, wn = (warp & 1) * 32;
    int lr = lane >> 2, lc = lane & 3;

    int arow = tid >> 1, acs = (tid & 1) * 2;
    int brow = tid >> 2, bcs = tid & 3;
    uint32_t aDst = arow * PITCH + acs * 16;
    uint32_t bDst = brow * PITCH + bcs * 16;
    long aRowOff = (long)(m0 + arow) * lda + aOff + acs * 8;
    long bSrc = bOff + (long)(n0 + brow) * ldb + bcs * 8;

    uint32_t aFrag = (uint32_t)((wm + (lane & 15)) * PITCH + (lane >> 4) * 16);
    uint32_t bFrag = (uint32_t)((wn + ((lane >> 4) << 3) + (lane & 7)) * PITCH
                                + ((lane >> 3) & 1) * 16);

    const int NCH = KTOT / 32;

    auto issue = [&](int ch, int st) {
        uint32_t sb = sm0 + st * STAGE;
        int c0 = ch * 32;
        const bf16* ah_ = Ah;
        const bf16* al_ = Al;
        int kk = c0;
        if (SPLITK < KTOT && c0 >= SPLITK) { ah_ = g_mh; al_ = g_ml; kk = c0 - SPLITK; }
        long ga = aRowOff + kk;
        CP16(sb + aDst,                ah_ + ga);
        CP16(sb + aDst + 16,           ah_ + ga + 8);
        CP16(sb + OFF_AL + aDst,       al_ + ga);
        CP16(sb + OFF_AL + aDst + 16,  al_ + ga + 8);
        long gb = bSrc + c0;
        CP16(sb + OFF_BH + bDst, g_wh + gb);
        CP16(sb + OFF_BL + bDst, g_wl + gb);
    };

    float acc[2][4][4];
    #pragma unroll
    for (int i = 0; i < 2; i++)
        #pragma unroll
        for (int j = 0; j < 4; j++)
            #pragma unroll
            for (int q = 0; q < 4; q++) acc[i][j][q] = 0.f;

    issue(0, 0);
    CP_COMMIT();
    if (NCH > 1) { issue(1, 1); CP_COMMIT(); }

    #pragma unroll
    for (int ch = 0; ch < NCH; ch++) {
        if (ch + 2 < NCH) { issue(ch + 2, (ch + 2) % NSTAGE); CP_COMMIT(); }
        if (ch + 2 < NCH)      CP_WAIT2();
        else if (ch + 1 < NCH) CP_WAIT1();
        else                   CP_WAIT0();
        __syncthreads();

        uint32_t sb = sm0 + (ch % NSTAGE) * STAGE;
        #pragma unroll
        for (int ks = 0; ks < 2; ks++) {
            uint32_t kb = ks * 32;
            uint32_t ah[2][4], al[2][4], bh[2][4], bl[2][4];
            #pragma unroll
            for (int am = 0; am < 2; am++) {
                ldmx4(ah[am], sb + aFrag + am * (16 * PITCH) + kb);
                ldmx4(al[am], sb + OFF_AL + aFrag + am * (16 * PITCH) + kb);
            }
            #pragma unroll
            for (int anp = 0; anp < 2; anp++) {
                ldmx4(bh[anp], sb + OFF_BH + bFrag + anp * (16 * PITCH) + kb);
                ldmx4(bl[anp], sb + OFF_BL + bFrag + anp * (16 * PITCH) + kb);
            }
            #pragma unroll
            for (int am = 0; am < 2; am++)
                #pragma unroll
                for (int an = 0; an < 4; an++) {
                    const uint32_t* bph = &bh[an >> 1][(an & 1) * 2];
                    const uint32_t* bpl = &bl[an >> 1][(an & 1) * 2];
                    mma16816(acc[am][an], ah[am], bph);
                    mma16816(acc[am][an], ah[am], bpl);
                    mma16816(acc[am][an], al[am], bph);
                }
        }
        __syncthreads();
    }

    // ---- epilogue ----
    #pragma unroll
    for (int am = 0; am < 2; am++) {
        #pragma unroll
        for (int an = 0; an < 4; an++) {
            int row0 = m0 + wm + am * 16 + lr;
            int col  = n0 + wn + an * 8 + lc * 2;
            float b0 = 0.f, b1 = 0.f;
            if (bias) {
                b0 = bias[biasZ * z + col];
                b1 = bias[biasZ * z + col + 1];
            }
            float v0 = acc[am][an][0] + b0, v1 = acc[am][an][1] + b1;
            float v2 = acc[am][an][2] + b0, v3 = acc[am][an][3] + b1;
            if (ACT == 1) {
                v0 = fmaxf(v0, 0.f); v1 = fmaxf(v1, 0.f);
                v2 = fmaxf(v2, 0.f); v3 = fmaxf(v3, 0.f);
            }
            long off = (long)cZ * z + col;
            if (CBF) {
                bf16* Ch = (CBF == 1) ? g_qh : g_ch;
                bf16* Cl = (CBF == 1) ? g_ql : g_cl;
                long p0 = (long)row0 * ldc + off;
                long p1 = (long)(row0 + 8) * ldc + off;
                store_split(Ch + p0, Cl + p0, v0);
                store_split(Ch + p0 + 1, Cl + p0 + 1, v1);
                store_split(Ch + p1, Cl + p1, v2);
                store_split(Ch + p1 + 1, Cl + p1 + 1, v3);
            } else {
                *(float2*)(Cf + (long)row0 * ldc + off) = make_float2(v0, v1);
                *(float2*)(Cf + (long)(row0 + 8) * ldc + off) = make_float2(v2, v3);
            }
        }
    }
}

#define NOSPLIT (1 << 30)

// ---------------------------------------------------------------------------
extern "C" void kernel_launch(void* const* d_in, const int* in_sizes, int n_in,
                              void* d_out, int out_size) {
    const float* storage = (const float*)d_in[0];
    const float* x       = (const float*)d_in[1];
    const float* ad_w1   = (const float*)d_in[2];
    const float* ad_b1   = (const float*)d_in[3];
    const float* ad_w2   = (const float*)d_in[4];
    const float* ad_b2   = (const float*)d_in[5];
    const float* imp_w1  = (const float*)d_in[6];
    const float* imp_b1  = (const float*)d_in[7];
    const float* imp_w2  = (const float*)d_in[8];
    const float* imp_b2  = (const float*)d_in[9];
    const float* w_in    = (const float*)d_in[10];
    const float* b_in    = (const float*)d_in[11];
    const float* w_out   = (const float*)d_in[12];
    const float* b_out   = (const float*)d_in[13];

    float* st  = (float*)d_out;                       // [B,K,D]
    float* agg = st + (long)BATCH * KS * DIM;         // [B,D]

    cudaFuncSetAttribute(gemm_pl<1, 256, NOSPLIT, 1, 0>,
                         cudaFuncAttributeMaxDynamicSharedMemorySize, SMEM_DYN);
    cudaFuncSetAttribute(gemm_pl<3, 64, NOSPLIT, 0, 0>,
                         cudaFuncAttributeMaxDynamicSharedMemorySize, SMEM_DYN);
    cudaFuncSetAttribute(gemm_pl<1, 256, NOSPLIT, 0, 1>,
                         cudaFuncAttributeMaxDynamicSharedMemorySize, SMEM_DYN);
    cudaFuncSetAttribute(gemm_pl<2, 512, 256, 0, 1>,
                         cudaFuncAttributeMaxDynamicSharedMemorySize, SMEM_DYN);
    cudaFuncSetAttribute(gemm_pl<4, 256, NOSPLIT, 2, 0>,
                         cudaFuncAttributeMaxDynamicSharedMemorySize, SMEM_DYN);
    cudaFuncSetAttribute(gemm_pl<5, 256, NOSPLIT, 0, 0>,
                         cudaFuncAttributeMaxDynamicSharedMemorySize, SMEM_DYN);

    conv_w<<<(W_TOTAL + 255) / 256, 256>>>(ad_w1, imp_w1, w_in, w_out);
    conv_x<<<BATCH, 256>>>(x);
    // q = x @ wq^T + bq -> g_qh/g_ql [B,256]
    gemm_pl<1, 256, NOSPLIT, 1, 0><<<dim3(128, 4, 1), 256, SMEM_DYN>>>(
        256, 0, 163840, 256, 0, b_in, 0, nullptr, 0, 256, 0);
    // qk[b, z*256+n] = wkT[z][n][:] . q[b, z*64:] -> g_qk fp32
    gemm_pl<3, 64, NOSPLIT, 0, 0><<<dim3(128, 4, 4), 256, SMEM_DYN>>>(
        256, 64, 229376, 64, 16384, nullptr, 0, nullptr, 5, 1024, 256);
    // stats + st rows 1..19 + attention partials (N1, Z1, dot0)
    k1_stats<<<BATCH, 256>>>(storage, x, st);
    // ad-MLP hidden: relu(x @ ad_w1^T + ad_b1) -> g_had [B,128]
    gemm_pl<1, 256, NOSPLIT, 0, 1><<<dim3(128, 2, 1), 256, SMEM_DYN>>>(
        256, 0, 0, 256, 0, ad_b1, 0, nullptr, 2, 128, 0);
    // imp-MLP hidden: relu([x|hmean] @ imp_w1^T + imp_b1) -> g_himp [B,256]
    gemm_pl<2, 512, 256, 0, 1><<<dim3(128, 4, 1), 256, SMEM_DYN>>>(
        256, 0, 32768, 512, 0, imp_b1, 0, nullptr, 3, 256, 0);
    // anomaly + importance + st row0 + final weighted sums -> g_sh/g_sl
    kf<<<BATCH, 256>>>(ad_w2, ad_b2, imp_w2, imp_b2, x, st);
    // ctx[b, z*64+n] = wv_z[n,:] . s[b,z,:] + bv -> g_ch/g_cl [B,256]
    gemm_pl<4, 256, NOSPLIT, 2, 0><<<dim3(128, 1, 4), 256, SMEM_DYN>>>(
        1024, 256, 294912, 256, 16384, b_in + 512, 64, nullptr, 0, 256, 64);
    // agg = ctx @ attn_out_w^T + attn_out_b -> d_out tail (fp32)
    gemm_pl<5, 256, NOSPLIT, 0, 0><<<dim3(128, 4, 1), 256, SMEM_DYN>>>(
        256, 0, 360448, 256, 0, b_out, 0, agg, 0, 256, 0);
    (void)in_sizes; (void)n_in; (void)out_size;
}

// round 10
// speedup vs baseline: 1.2720x; 1.0233x over previous
#include <cuda_runtime.h>
#include <cuda_bf16.h>
#include <stdint.h>

#define BATCH 16384
#define KS 20
#define DIM 256
#define NH 4
#define EPSF 1e-8f

typedef __nv_bfloat16 bf16;

// ---------------- scratch (device globals; allocations are forbidden) ------
__device__ bf16 g_xh [(long)BATCH * 256], g_xl [(long)BATCH * 256];
__device__ bf16 g_mh [(long)BATCH * 256], g_ml [(long)BATCH * 256];  // hmean
__device__ bf16 g_qh [(long)BATCH * 256], g_ql [(long)BATCH * 256];
__device__ bf16 g_sh [(long)BATCH * 1024], g_sl [(long)BATCH * 1024];
__device__ bf16 g_ch [(long)BATCH * 256], g_cl [(long)BATCH * 256];
#define W_TOTAL 425984
__device__ bf16 g_wh[W_TOTAL], g_wl[W_TOTAL];
__device__ float g_had [(long)BATCH * 128];
__device__ float g_himp[(long)BATCH * 256];
__device__ float g_qk  [(long)BATCH * 1024];
__device__ float g_N   [(long)BATCH * 1024];
__device__ float g_Z   [(long)BATCH * NH];
__device__ float g_dot0[(long)BATCH * NH];
__device__ float g_stat[BATCH];

__device__ __forceinline__ float warp_sum(float v) {
    #pragma unroll
    for (int o = 16; o; o >>= 1) v += __shfl_down_sync(0xffffffffu, v, o);
    return v;
}
__device__ __forceinline__ void store_split(bf16* ph, bf16* pl, float v) {
    bf16 h = __float2bfloat16(v);
    *ph = h;
    *pl = __float2bfloat16(v - __bfloat162float(h));
}

// ---------------- conv: weights (new layout) + x, one launch ---------------
// layout in g_wh/g_wl:
//   [0,65536)        wq      [256][256]
//   [65536,98304)    ad_w1   [128][256]
//   [98304,229376)   imp_w1  [256][512]
//   [229376,294912)  wkT     [4][256 n][64 i]   (transposed)
//   [294912,360448)  wv      [256][256]
//   [360448,425984)  w_out   [256][256]
#define CONV_TOTAL (W_TOTAL + BATCH * 256)
__global__ __launch_bounds__(256) void conv_all(
    const float* __restrict__ ad_w1, const float* __restrict__ imp_w1,
    const float* __restrict__ w_in,  const float* __restrict__ w_out,
    const float* __restrict__ x)
{
    long i = (long)blockIdx.x * 256 + threadIdx.x;
    if (i >= CONV_TOTAL) return;
    if (i >= W_TOTAL) {
        long idx = i - W_TOTAL;
        store_split(g_xh + idx, g_xl + idx, x[idx]);
        return;
    }
    int ii = (int)i;
    float v;
    if (ii < 65536)       v = w_in[ii];
    else if (ii < 98304)  v = ad_w1[ii - 65536];
    else if (ii < 229376) v = imp_w1[ii - 98304];
    else if (ii < 294912) {
        int j = ii - 229376;
        int z = j >> 14, r = (j >> 6) & 255, c = j & 63;
        v = w_in[65536 + (z * 64 + c) * 256 + r];
    }
    else if (ii < 360448) v = w_in[131072 + (ii - 294912)];
    else                  v = w_out[ii - 360448];
    bf16 h = __float2bfloat16(v);
    g_wh[ii] = h;
    g_wl[ii] = __float2bfloat16(v - __bfloat162float(h));
}

// ---------------- K1: stats + st rows 1..19 + attention partials -----------
__global__ __launch_bounds__(256) void k1_stats(
    const float* __restrict__ storage, const float* __restrict__ xmsg,
    float* __restrict__ out_st)
{
    __shared__ float sm[KS][DIM];
    __shared__ float qks[NH * DIM];
    __shared__ float xs[DIM];
    __shared__ float smask[KS];
    __shared__ float sred[8];
    __shared__ float sc[NH][KS];

    int b = blockIdx.x, tid = threadIdx.x;
    const float* row = storage + (long)b * KS * DIM;
    float vals[KS];
    #pragma unroll
    for (int j = 0; j < KS; j++) {
        vals[j] = row[j * DIM + tid];
        sm[j][tid] = vals[j];
    }
    xs[tid] = xmsg[(long)b * DIM + tid];
    #pragma unroll
    for (int h = 0; h < NH; h++)
        qks[h * DIM + tid] = g_qk[(long)b * 1024 + h * DIM + tid];
    __syncthreads();

    int w = tid >> 5, lane = tid & 31;
    for (int j = w; j < KS; j += 8) {
        const float4* sj = (const float4*)sm[j];
        float4 a = sj[lane], c = sj[lane + 32];
        float s = fabsf(a.x) + fabsf(a.y) + fabsf(a.z) + fabsf(a.w)
                + fabsf(c.x) + fabsf(c.y) + fabsf(c.z) + fabsf(c.w);
        s = warp_sum(s);
        if (lane == 0) smask[j] = (s > 0.f) ? 1.f : 0.f;
    }
    __syncthreads();

    float denom = EPSF;
    #pragma unroll
    for (int j = 0; j < KS; j++) denom += smask[j];

    int d = tid;
    float m = 0.f;
    #pragma unroll
    for (int j = 0; j < KS; j++) m += vals[j] * smask[j];
    float hmean = m / denom;
    float v = 0.f;
    #pragma unroll
    for (int j = 0; j < KS; j++) {
        float df = vals[j] - hmean;
        v += df * df * smask[j];
    }
    float hstd = sqrtf(v / denom);

    float xd = xs[d];
    float z = fabsf((xd - hmean) / (hstd + EPSF));
    float c = (z > 2.0f) ? 1.f : 0.f;
    c = warp_sum(c);
    if (lane == 0) sred[w] = c;
    __syncthreads();
    if (tid == 0) {
        float t = 0.f;
        #pragma unroll
        for (int i = 0; i < 8; i++) t += sred[i];
        g_stat[b] = t / (float)DIM;
    }

    store_split(g_mh + (long)b * 256 + d, g_ml + (long)b * 256 + d, hmean);

    float dec = 1.f;
    float* orow = out_st + (long)b * KS * DIM;
    #pragma unroll
    for (int jj = 0; jj < KS - 1; jj++) {
        float sv = vals[jj] * dec;
        vals[jj] = sv;
        sm[jj][d] = sv;
        orow[(jj + 1) * DIM + d] = sv;
        dec *= 0.95f;
    }
    __syncthreads();

    #pragma unroll
    for (int u = 0; u < 10; u++) {
        int id = w + u * 8;
        if (id < 76) {
            int h = id / 19, jj = id % 19;
            const float4* qh = (const float4*)(qks + h * DIM);
            const float4* sj = (const float4*)sm[jj];
            float4 a0 = qh[lane],      b0 = sj[lane];
            float4 a1 = qh[lane + 32], b1 = sj[lane + 32];
            float s = a0.x * b0.x + a0.y * b0.y + a0.z * b0.z + a0.w * b0.w
                    + a1.x * b1.x + a1.y * b1.y + a1.z * b1.z + a1.w * b1.w;
            s = warp_sum(s);
            if (lane == 0) sc[h][jj] = expf(s * 0.125f);
        } else {
            int h = id - 76;
            const float4* qh = (const float4*)(qks + h * DIM);
            const float4* xv = (const float4*)xs;
            float4 a0 = qh[lane],      b0 = xv[lane];
            float4 a1 = qh[lane + 32], b1 = xv[lane + 32];
            float s = a0.x * b0.x + a0.y * b0.y + a0.z * b0.z + a0.w * b0.w
                    + a1.x * b1.x + a1.y * b1.y + a1.z * b1.z + a1.w * b1.w;
            s = warp_sum(s);
            if (lane == 0) g_dot0[(long)b * NH + h] = s * 0.125f;
        }
    }
    __syncthreads();

    if (tid < NH) {
        float zz = 0.f;
        #pragma unroll
        for (int jj = 0; jj < KS - 1; jj++) zz += sc[tid][jj];
        g_Z[(long)b * NH + tid] = zz;
    }

    float acc[NH] = {0.f, 0.f, 0.f, 0.f};
    #pragma unroll
    for (int jj = 0; jj < KS - 1; jj++) {
        float sv = vals[jj];
        #pragma unroll
        for (int h = 0; h < NH; h++) acc[h] += sc[h][jj] * sv;
    }
    #pragma unroll
    for (int h = 0; h < NH; h++)
        g_N[(long)b * 1024 + h * DIM + d] = acc[h];
}

// ---------------- kf: anomaly + importance + st row0 + final attention -----
__global__ __launch_bounds__(256) void kf(
    const float* __restrict__ ad_w2, const float* __restrict__ ad_b2,
    const float* __restrict__ imp_w2, const float* __restrict__ imp_b2,
    const float* __restrict__ xmsg, float* __restrict__ out_st)
{
    __shared__ float sred1[8], sred2[8], se0[NH], sfac[NH];
    __shared__ float simp;
    int b = blockIdx.x, tid = threadIdx.x;
    int w = tid >> 5, lane = tid & 31;

    float p1 = (tid < 128) ? g_had[(long)b * 128 + tid] * ad_w2[tid] : 0.f;
    float p2 = g_himp[(long)b * 256 + tid] * imp_w2[tid];
    p1 = warp_sum(p1);
    p2 = warp_sum(p2);
    if (lane == 0) { sred1[w] = p1; sred2[w] = p2; }
    __syncthreads();
    if (tid == 0) {
        float d1 = ad_b2[0], d2 = imp_b2[0];
        #pragma unroll
        for (int i = 0; i < 8; i++) { d1 += sred1[i]; d2 += sred2[i]; }
        float learned = 1.f / (1.f + expf(-d1));
        float anom = 0.5f * g_stat[b] + 0.5f * learned;
        float sp = fmaxf(d2, 0.f) + log1pf(expf(-fabsf(d2)));
        simp = sp * (1.f + anom);
    }
    __syncthreads();
    float imp = simp;
    if (tid < NH) {
        float e0 = expf(imp * g_dot0[(long)b * NH + tid]);
        se0[tid] = e0;
        sfac[tid] = 1.f / (g_Z[(long)b * NH + tid] + e0);
    }
    float x = xmsg[(long)b * 256 + tid];
    float st0 = x * imp;
    out_st[(long)b * KS * DIM + tid] = st0;
    __syncthreads();

    #pragma unroll
    for (int h = 0; h < NH; h++) {
        float s = (g_N[(long)b * 1024 + h * 256 + tid] + se0[h] * st0) * sfac[h];
        long o = (long)b * 1024 + h * 256 + tid;
        store_split(g_sh + o, g_sl + o, s);
    }
}

// ---------------- pipelined bf16x3 TC GEMM, 128x64 tile --------------------
#define PITCH 80
#define SZ_A 10240
#define SZ_B 5120
#define OFF_AL (SZ_A)
#define OFF_BH (2 * SZ_A)
#define OFF_BL (2 * SZ_A + SZ_B)
#define STAGE  (2 * SZ_A + 2 * SZ_B)   // 30720
#define SMEM_DYN (2 * STAGE)           // 61440 (NST=2)

#define CP16(dst, src) asm volatile( \
    "cp.async.cg.shared.global [%0], [%1], 16;" :: "r"(dst), "l"(src))
#define CP_COMMIT() asm volatile("cp.async.commit_group;" ::: "memory")
#define CP_WAIT1()  asm volatile("cp.async.wait_group 1;" ::: "memory")
#define CP_WAIT0()  asm volatile("cp.async.wait_group 0;" ::: "memory")

__device__ __forceinline__ void ldmx4(uint32_t* r, uint32_t addr) {
    asm volatile("ldmatrix.sync.aligned.m8n8.x4.shared.b16 {%0,%1,%2,%3},[%4];"
                 : "=r"(r[0]), "=r"(r[1]), "=r"(r[2]), "=r"(r[3]) : "r"(addr));
}
__device__ __forceinline__ void mma16816(float* c, const uint32_t* a,
                                         const uint32_t* b) {
    asm volatile(
        "mma.sync.aligned.m16n8k16.row.col.f32.bf16.bf16.f32 "
        "{%0,%1,%2,%3},{%4,%5,%6,%7},{%8,%9},{%0,%1,%2,%3};"
        : "+f"(c[0]), "+f"(c[1]), "+f"(c[2]), "+f"(c[3])
        : "r"(a[0]), "r"(a[1]), "r"(a[2]), "r"(a[3]), "r"(b[0]), "r"(b[1]));
}
__device__ __forceinline__ uint32_t smem_u32(const void* p) {
    return (uint32_t)__cvta_generic_to_shared(p);
}

// MERGED=1: q+ad fused (n0<256 -> bf16 q pairs; n0>=256 -> relu fp32 g_had)
template<int ASEL, int KTOT, int SPLITK, int CBF, int ACT, int MERGED>
__global__ __launch_bounds__(256, 3) void gemm_pl(
    int lda, int aZ, int wOff, int ldb, int bZ,
    const float* __restrict__ bias, const float* __restrict__ bias2,
    int biasZ, float* __restrict__ Cext, int cSel, int ldc, int cZ)
{
    extern __shared__ __align__(128) char dsm[];
    uint32_t sm0 = smem_u32(dsm);
    const int NST = 2;

    const bf16 *Ah, *Al;
    if (ASEL == 1 || ASEL == 2) { Ah = g_xh; Al = g_xl; }
    else if (ASEL == 3) { Ah = g_qh; Al = g_ql; }
    else if (ASEL == 4) { Ah = g_sh; Al = g_sl; }
    else                { Ah = g_ch; Al = g_cl; }
    float* Cf = Cext;
    if (cSel == 2) Cf = g_had;
    else if (cSel == 3) Cf = g_himp;
    else if (cSel == 5) Cf = g_qk;

    int z  = blockIdx.z;
    int m0 = blockIdx.x * 128;
    int n0 = blockIdx.y * 64;
    long aOff = (long)aZ * z;
    long bOff = (long)wOff + (long)bZ * z;

    int tid = threadIdx.x;
    int warp = tid >> 5, lane = tid & 31;
    int wm = (warp >> 1) * 32, wn = (warp & 1) * 32;
    int lr = lane >> 2, lc = lane & 3;

    int arow = tid >> 1, acs = (tid & 1) * 2;
    int brow = tid >> 2, bcs = tid & 3;
    uint32_t aDst = arow * PITCH + acs * 16;
    uint32_t bDst = brow * PITCH + bcs * 16;
    long aRowOff = (long)(m0 + arow) * lda + aOff + acs * 8;
    long bSrc = bOff + (long)(n0 + brow) * ldb + bcs * 8;

    uint32_t aFrag = (uint32_t)((wm + (lane & 15)) * PITCH + (lane >> 4) * 16);
    uint32_t bFrag = (uint32_t)((wn + ((lane >> 4) << 3) + (lane & 7)) * PITCH
                                + ((lane >> 3) & 1) * 16);

    const int NCH = KTOT / 32;

    auto issue = [&](int ch, int st) {
        uint32_t sb = sm0 + st * STAGE;
        int c0 = ch * 32;
        const bf16* ah_ = Ah;
        const bf16* al_ = Al;
        int kk = c0;
        if (SPLITK < KTOT && c0 >= SPLITK) { ah_ = g_mh; al_ = g_ml; kk = c0 - SPLITK; }
        long ga = aRowOff + kk;
        CP16(sb + aDst,                ah_ + ga);
        CP16(sb + aDst + 16,           ah_ + ga + 8);
        CP16(sb + OFF_AL + aDst,       al_ + ga);
        CP16(sb + OFF_AL + aDst + 16,  al_ + ga + 8);
        long gb = bSrc + c0;
        CP16(sb + OFF_BH + bDst, g_wh + gb);
        CP16(sb + OFF_BL + bDst, g_wl + gb);
    };

    float acc[2][4][4];
    #pragma unroll
    for (int i = 0; i < 2; i++)
        #pragma unroll
        for (int j = 0; j < 4; j++)
            #pragma unroll
            for (int q = 0; q < 4; q++) acc[i][j][q] = 0.f;

    // prologue: NST-1 chunks in flight
    issue(0, 0);
    CP_COMMIT();

    #pragma unroll
    for (int ch = 0; ch < NCH; ch++) {
        if (ch + NST - 1 < NCH) {
            issue(ch + NST - 1, (ch + NST - 1) % NST);
            CP_COMMIT();
        }
        int pend = ((ch + NST < NCH) ? (ch + NST) : NCH) - ch - 1;
        if (pend >= 1) CP_WAIT1(); else CP_WAIT0();
        __syncthreads();

        uint32_t sb = sm0 + (ch % NST) * STAGE;
        #pragma unroll
        for (int ks = 0; ks < 2; ks++) {
            uint32_t kb = ks * 32;
            uint32_t ah[2][4], al[2][4], bh[2][4], bl[2][4];
            #pragma unroll
            for (int am = 0; am < 2; am++) {
                ldmx4(ah[am], sb + aFrag + am * (16 * PITCH) + kb);
                ldmx4(al[am], sb + OFF_AL + aFrag + am * (16 * PITCH) + kb);
            }
            #pragma unroll
            for (int anp = 0; anp < 2; anp++) {
                ldmx4(bh[anp], sb + OFF_BH + bFrag + anp * (16 * PITCH) + kb);
                ldmx4(bl[anp], sb + OFF_BL + bFrag + anp * (16 * PITCH) + kb);
            }
            #pragma unroll
            for (int am = 0; am < 2; am++)
                #pragma unroll
                for (int an = 0; an < 4; an++) {
                    const uint32_t* bph = &bh[an >> 1][(an & 1) * 2];
                    const uint32_t* bpl = &bl[an >> 1][(an & 1) * 2];
                    mma16816(acc[am][an], ah[am], bph);
                    mma16816(acc[am][an], ah[am], bpl);
                    mma16816(acc[am][an], al[am], bph);
                }
        }
        __syncthreads();
    }

    // ---- epilogue ----
    bool adPath = MERGED && (n0 >= 256);
    #pragma unroll
    for (int am = 0; am < 2; am++) {
        #pragma unroll
        for (int an = 0; an < 4; an++) {
            int row0 = m0 + wm + am * 16 + lr;
            int col  = n0 + wn + an * 8 + lc * 2;
            float v0 = acc[am][an][0], v1 = acc[am][an][1];
            float v2 = acc[am][an][2], v3 = acc[am][an][3];
            if (adPath) {
                int cc = col - 256;
                float b0 = bias2[cc], b1 = bias2[cc + 1];
                v0 = fmaxf(v0 + b0, 0.f); v1 = fmaxf(v1 + b1, 0.f);
                v2 = fmaxf(v2 + b0, 0.f); v3 = fmaxf(v3 + b1, 0.f);
                *(float2*)(g_had + (long)row0 * 128 + cc) = make_float2(v0, v1);
                *(float2*)(g_had + (long)(row0 + 8) * 128 + cc) = make_float2(v2, v3);
            } else {
                float b0 = 0.f, b1 = 0.f;
                if (bias) {
                    b0 = bias[biasZ * z + col];
                    b1 = bias[biasZ * z + col + 1];
                }
                v0 += b0; v1 += b1; v2 += b0; v3 += b1;
                if (ACT == 1) {
                    v0 = fmaxf(v0, 0.f); v1 = fmaxf(v1, 0.f);
                    v2 = fmaxf(v2, 0.f); v3 = fmaxf(v3, 0.f);
                }
                long off = (long)cZ * z + col;
                if (CBF) {
                    bf16* Ch = (CBF == 1) ? g_qh : g_ch;
                    bf16* Cl = (CBF == 1) ? g_ql : g_cl;
                    long p0 = (long)row0 * ldc + off;
                    long p1 = (long)(row0 + 8) * ldc + off;
                    store_split(Ch + p0, Cl + p0, v0);
                    store_split(Ch + p0 + 1, Cl + p0 + 1, v1);
                    store_split(Ch + p1, Cl + p1, v2);
                    store_split(Ch + p1 + 1, Cl + p1 + 1, v3);
                } else {
                    *(float2*)(Cf + (long)row0 * ldc + off) = make_float2(v0, v1);
                    *(float2*)(Cf + (long)(row0 + 8) * ldc + off) = make_float2(v2, v3);
                }
            }
        }
    }
}

#define NOSPLIT (1 << 30)

// ---------------------------------------------------------------------------
extern "C" void kernel_launch(void* const* d_in, const int* in_sizes, int n_in,
                              void* d_out, int out_size) {
    const float* storage = (const float*)d_in[0];
    const float* x       = (const float*)d_in[1];
    const float* ad_w1   = (const float*)d_in[2];
    const float* ad_b1   = (const float*)d_in[3];
    const float* ad_w2   = (const float*)d_in[4];
    const float* ad_b2   = (const float*)d_in[5];
    const float* imp_w1  = (const float*)d_in[6];
    const float* imp_b1  = (const float*)d_in[7];
    const float* imp_w2  = (const float*)d_in[8];
    const float* imp_b2  = (const float*)d_in[9];
    const float* w_in    = (const float*)d_in[10];
    const float* b_in    = (const float*)d_in[11];
    const float* w_out   = (const float*)d_in[12];
    const float* b_out   = (const float*)d_in[13];

    float* st  = (float*)d_out;                       // [B,K,D]
    float* agg = st + (long)BATCH * KS * DIM;         // [B,D]

    cudaFuncSetAttribute(gemm_pl<1, 256, NOSPLIT, 1, 0, 1>,
                         cudaFuncAttributeMaxDynamicSharedMemorySize, SMEM_DYN);
    cudaFuncSetAttribute(gemm_pl<3, 64, NOSPLIT, 0, 0, 0>,
                         cudaFuncAttributeMaxDynamicSharedMemorySize, SMEM_DYN);
    cudaFuncSetAttribute(gemm_pl<2, 512, 256, 0, 1, 0>,
                         cudaFuncAttributeMaxDynamicSharedMemorySize, SMEM_DYN);
    cudaFuncSetAttribute(gemm_pl<4, 256, NOSPLIT, 2, 0, 0>,
                         cudaFuncAttributeMaxDynamicSharedMemorySize, SMEM_DYN);
    cudaFuncSetAttribute(gemm_pl<5, 256, NOSPLIT, 0, 0, 0>,
                         cudaFuncAttributeMaxDynamicSharedMemorySize, SMEM_DYN);

    // weights (new layout) + x split, one launch
    conv_all<<<(CONV_TOTAL + 255) / 256, 256>>>(ad_w1, imp_w1, w_in, w_out, x);
    // MERGED q+ad: cols 0..255 -> q (bf16 pairs, bias b_in); 256..383 -> ad hidden
    gemm_pl<1, 256, NOSPLIT, 1, 0, 1><<<dim3(128, 6, 1), 256, SMEM_DYN>>>(
        256, 0, 0, 256, 0, b_in, ad_b1, 0, nullptr, 0, 256, 0);
    // qk[b, z*256+n] = wkT[z][n][:] . q[b, z*64:] -> g_qk fp32
    gemm_pl<3, 64, NOSPLIT, 0, 0, 0><<<dim3(128, 4, 4), 256, SMEM_DYN>>>(
        256, 64, 229376, 64, 16384, nullptr, nullptr, 0, nullptr, 5, 1024, 256);
    // stats + st rows 1..19 + attention partials (N1, Z1, dot0)
    k1_stats<<<BATCH, 256>>>(storage, x, st);
    // imp-MLP hidden: relu([x|hmean] @ imp_w1^T + imp_b1) -> g_himp [B,256]
    gemm_pl<2, 512, 256, 0, 1, 0><<<dim3(128, 4, 1), 256, SMEM_DYN>>>(
        256, 0, 98304, 512, 0, imp_b1, nullptr, 0, nullptr, 3, 256, 0);
    // anomaly + importance + st row0 + final weighted sums -> g_sh/g_sl
    kf<<<BATCH, 256>>>(ad_w2, ad_b2, imp_w2, imp_b2, x, st);
    // ctx[b, z*64+n] = wv_z[n,:] . s[b,z,:] + bv -> g_ch/g_cl [B,256]
    gemm_pl<4, 256, NOSPLIT, 2, 0, 0><<<dim3(128, 1, 4), 256, SMEM_DYN>>>(
        1024, 256, 294912, 256, 16384, b_in + 512, nullptr, 64, nullptr, 0, 256, 64);
    // agg = ctx @ attn_out_w^T + attn_out_b -> d_out tail (fp32)
    gemm_pl<5, 256, NOSPLIT, 0, 0, 0><<<dim3(128, 4, 1), 256, SMEM_DYN>>>(
        256, 0, 360448, 256, 0, b_out, nullptr, 0, agg, 0, 256, 0);
    (void)in_sizes; (void)n_in; (void)out_size;
}